// round 2
// baseline (speedup 1.0000x reference)
#include <cuda_runtime.h>
#include <cstdint>

// ============================================================================
// StableFourierConvSSM fused kernel, round 2 (resubmit of round-1 design;
// round-1 bench died to an infra container failure with no kernel verdict).
// Shapes: B=16, H=128, W=128, C=64, C2=128, K=7, T=16.
//
// Pipeline (3 launches, one stream, graph-capturable, no allocations):
//   1) freq_rows : separable DFT stage 1 (over p) of zero-padded 7x7 kernels
//   2) freq_cols : stage 2 (over q) + stability scaling of A  -> g_Ar/Ai/Br/Bi
//   3) fused_main: per (b,h) CTA:
//        - stage x row-tile (128x128 fp32) in smem
//        - 3 gate GEMMs (Zf, Zi, Zd) via mma.sync.m16n8k8 tf32, W columns
//          permuted so each thread's accumulator fragment holds matched
//          (real c, imag c+64) pairs -> gates never leave registers
//        - activations + complex input term + T=16 recurrence in registers
//        - write output
// ============================================================================

#define SX_STRIDE 132   // 128 cols + pad: conflict-free A-frag loads
#define SW_STRIDE 72    // conflict-free B-frag loads
#define SMEM_FLOATS (128 * SX_STRIDE + 128 * SW_STRIDE + 384)
#define SMEM_BYTES (SMEM_FLOATS * 4)

// Frequency-domain kernels, layout [h][w][c] (c contiguous)
__device__ float g_Ar[128 * 128 * 64];
__device__ float g_Ai[128 * 128 * 64];
__device__ float g_Br[128 * 128 * 64];
__device__ float g_Bi[128 * 128 * 64];
// Separable-DFT intermediate, layout [(u*7+q)*64 + c]
__device__ float g_GAr[128 * 7 * 64];
__device__ float g_GAi[128 * 7 * 64];
__device__ float g_GBr[128 * 7 * 64];
__device__ float g_GBi[128 * 7 * 64];

__device__ __forceinline__ uint32_t f2tf32(float x) {
    uint32_t u;
    asm("cvt.rna.tf32.f32 %0, %1;" : "=r"(u) : "f"(x));
    return u;
}

__device__ __forceinline__ void mma_tf32(float d[4], const uint32_t a[4],
                                         uint32_t b0, uint32_t b1) {
    asm("mma.sync.aligned.m16n8k8.row.col.f32.tf32.tf32.f32 "
        "{%0,%1,%2,%3}, {%4,%5,%6,%7}, {%8,%9}, {%0,%1,%2,%3};"
        : "+f"(d[0]), "+f"(d[1]), "+f"(d[2]), "+f"(d[3])
        : "r"(a[0]), "r"(a[1]), "r"(a[2]), "r"(a[3]), "r"(b0), "r"(b1));
}

__device__ __forceinline__ float sigm(float z) { return 1.0f / (1.0f + expf(-z)); }
__device__ __forceinline__ float softplus_f(float z) {
    return (z > 20.0f) ? z : log1pf(expf(z));
}

// ---------------------------------------------------------------------------
// Stage 1: G[c,u,q] = sum_p kern[c,p,q] * exp(-2*pi*i * u*(p+60)/128)
// grid = 128*7 blocks (u,q), 64 threads (c)
// ---------------------------------------------------------------------------
__global__ void freq_rows(const float* __restrict__ A_real, const float* __restrict__ A_imag,
                          const float* __restrict__ B_real, const float* __restrict__ B_imag) {
    __shared__ float tc[128], ts[128];
    int t = threadIdx.x;  // 64 threads
    for (int k = t; k < 128; k += 64) {
        float s, c;
        sincospif((float)k / 64.0f, &s, &c);  // angle = 2*pi*k/128
        tc[k] = c; ts[k] = s;
    }
    __syncthreads();

    int u = blockIdx.x / 7;
    int q = blockIdx.x % 7;
    int c = t;

    float gar = 0.f, gai = 0.f, gbr = 0.f, gbi = 0.f;
#pragma unroll
    for (int p = 0; p < 7; ++p) {
        int idx = (u * (p + 60)) & 127;
        float co = tc[idx], si = ts[idx];  // exp(-i*theta) = co - i*si
        float kr = A_real[c * 49 + p * 7 + q];
        float ki = A_imag[c * 49 + p * 7 + q];
        gar += kr * co + ki * si;
        gai += ki * co - kr * si;
        kr = B_real[c * 49 + p * 7 + q];
        ki = B_imag[c * 49 + p * 7 + q];
        gbr += kr * co + ki * si;
        gbi += ki * co - kr * si;
    }
    int o = (u * 7 + q) * 64 + c;
    g_GAr[o] = gar; g_GAi[o] = gai; g_GBr[o] = gbr; g_GBi[o] = gbi;
}

// ---------------------------------------------------------------------------
// Stage 2: F[c,u,v] = sum_q G[c,u,q] * exp(-2*pi*i * v*(q+60)/128),
// then stability-scale A. grid = 128*128 blocks (u,v), 64 threads (c)
// ---------------------------------------------------------------------------
__global__ void freq_cols() {
    __shared__ float tc[128], ts[128];
    int t = threadIdx.x;  // 64 threads
    for (int k = t; k < 128; k += 64) {
        float s, c;
        sincospif((float)k / 64.0f, &s, &c);
        tc[k] = c; ts[k] = s;
    }
    __syncthreads();

    int u = blockIdx.x >> 7;
    int v = blockIdx.x & 127;
    int c = t;

    float ar = 0.f, ai = 0.f, br = 0.f, bi = 0.f;
#pragma unroll
    for (int q = 0; q < 7; ++q) {
        int idx = (v * (q + 60)) & 127;
        float co = tc[idx], si = ts[idx];
        int o = (u * 7 + q) * 64 + c;
        float gr = g_GAr[o], gi = g_GAi[o];
        ar += gr * co + gi * si;
        ai += gi * co - gr * si;
        gr = g_GBr[o]; gi = g_GBi[o];
        br += gr * co + gi * si;
        bi += gi * co - gr * si;
    }
    float mag = sqrtf(ar * ar + ai * ai + 1e-8f);
    float sc = 0.95f * sigm(mag) / (mag + 1e-8f);
    int o = (u * 128 + v) * 64 + c;
    g_Ar[o] = ar * sc;
    g_Ai[o] = ai * sc;
    g_Br[o] = br;
    g_Bi[o] = bi;
}

// ---------------------------------------------------------------------------
// Fused main kernel. One CTA per (b,h): M=128 rows (w), K=128, N=3x128 gates.
// 256 threads = 8 warps: warp_m = warp>>1 (32-row strip), warp_n = warp&1.
// W columns permuted: smem col j -> channel m = hf*32 + (j>>1), orig col
// c = m + (j&1)*64, so (real,imag) of a channel sit in adjacent accumulator
// columns -> both land in the same thread (c0/c1 and c2/c3 of the C-frag).
// ---------------------------------------------------------------------------
__global__ void __launch_bounds__(256)
fused_main(const float* __restrict__ x,
           const float* __restrict__ Wf, const float* __restrict__ bf,
           const float* __restrict__ Wi, const float* __restrict__ bi,
           const float* __restrict__ Wd, const float* __restrict__ bd,
           float* __restrict__ out) {
    extern __shared__ float smem[];
    float* sX = smem;                          // [128][SX_STRIDE] raw fp32 x
    float* sW = sX + 128 * SX_STRIDE;          // [128][SW_STRIDE] tf32 panel
    float* sB = sW + 128 * SW_STRIDE;          // [384] biases

    const int tid = threadIdx.x;
    const int bid = blockIdx.x;
    const int b = bid >> 7;
    const int h = bid & 127;

    const float* xrow = x + ((size_t)(b * 128 + h) * 128) * 128;

    // stage x tile (coalesced float4)
    {
        const float4* x4 = (const float4*)xrow;
        for (int i = tid; i < 128 * 32; i += 256) {
            int r = i >> 5, c4 = i & 31;
            float4 v = x4[r * 32 + c4];
            float* d = sX + r * SX_STRIDE + c4 * 4;
            d[0] = v.x; d[1] = v.y; d[2] = v.z; d[3] = v.w;
        }
        for (int i = tid; i < 384; i += 256)
            sB[i] = (i < 128) ? bf[i] : (i < 256) ? bi[i - 128] : bd[i - 256];
    }

    const int lane = tid & 31;
    const int warp = tid >> 5;
    const int g = lane >> 2;       // groupID (row within 8)
    const int t4 = lane & 3;       // threadID in group
    const int wm = warp >> 1;      // 0..3 -> 32-row strip
    const int wn = warp & 1;       // 0..1 -> 32-col half of panel
    const int rbase = wm * 32;

    const float* Wg[3] = {Wf, Wi, Wd};

    for (int hf = 0; hf < 2; ++hf) {
        float acc[3][2][4][4];  // [gate][mtile][ntile][frag]

#pragma unroll
        for (int gate = 0; gate < 3; ++gate) {
            __syncthreads();  // previous pass done reading sW (and x staged)
            // load + permute + tf32-round W panel: K=128 x 64 cols
            const float* Wsrc = Wg[gate];
            for (int i = tid; i < 128 * 64; i += 256) {
                int k = i >> 6, j = i & 63;
                int c = hf * 32 + (j >> 1) + ((j & 1) << 6);
                sW[k * SW_STRIDE + j] = __uint_as_float(f2tf32(Wsrc[k * 128 + c]));
            }
            __syncthreads();

#pragma unroll
            for (int mt = 0; mt < 2; ++mt)
#pragma unroll
                for (int nt = 0; nt < 4; ++nt)
#pragma unroll
                    for (int r = 0; r < 4; ++r)
                        acc[gate][mt][nt][r] = 0.0f;

#pragma unroll 4
            for (int kt = 0; kt < 16; ++kt) {
                int k0 = kt * 8;
                uint32_t a[2][4];
#pragma unroll
                for (int mt = 0; mt < 2; ++mt) {
                    const float* ab = sX + (rbase + 16 * mt + g) * SX_STRIDE;
                    a[mt][0] = f2tf32(ab[k0 + t4]);
                    a[mt][1] = f2tf32(ab[8 * SX_STRIDE + k0 + t4]);
                    a[mt][2] = f2tf32(ab[k0 + t4 + 4]);
                    a[mt][3] = f2tf32(ab[8 * SX_STRIDE + k0 + t4 + 4]);
                }
#pragma unroll
                for (int nt = 0; nt < 4; ++nt) {
                    int jc = wn * 32 + nt * 8 + g;
                    uint32_t b0 = __float_as_uint(sW[(k0 + t4) * SW_STRIDE + jc]);
                    uint32_t b1 = __float_as_uint(sW[(k0 + t4 + 4) * SW_STRIDE + jc]);
                    mma_tf32(acc[gate][0][nt], a[0], b0, b1);
                    mma_tf32(acc[gate][1][nt], a[1], b0, b1);
                }
            }
        }

        // ---- epilogue: activations + complex input + T=16 recurrence ----
#pragma unroll
        for (int mt = 0; mt < 2; ++mt)
#pragma unroll
            for (int rr = 0; rr < 2; ++rr)
#pragma unroll
                for (int nt = 0; nt < 4; ++nt) {
                    const int w = rbase + 16 * mt + g + 8 * rr;
                    const int m = hf * 32 + wn * 16 + nt * 4 + t4;  // channel 0..63

                    float zf_r = acc[0][mt][nt][2 * rr];
                    float zf_i = acc[0][mt][nt][2 * rr + 1];
                    float zi_r = acc[1][mt][nt][2 * rr];
                    float zi_i = acc[1][mt][nt][2 * rr + 1];
                    float zd_r = acc[2][mt][nt][2 * rr];
                    float zd_i = acc[2][mt][nt][2 * rr + 1];

                    float fg_r = sigm(zf_r + sB[m] + 2.0f);
                    float fg_i = sigm(zf_i + sB[m + 64] + 2.0f);
                    float ig_r = sigm(zi_r + sB[128 + m]);
                    float ig_i = sigm(zi_i + sB[128 + m + 64]);
                    float dl_r = 0.1f * softplus_f(zd_r + sB[256 + m]);
                    float dl_i = 0.1f * softplus_f(zd_i + sB[256 + m + 64]);

                    float x_r = sX[w * SX_STRIDE + m];
                    float x_i = sX[w * SX_STRIDE + m + 64];

                    int fo = (h * 128 + w) * 64 + m;
                    float Ar = g_Ar[fo], Ai = g_Ai[fo];
                    float Br = g_Br[fo], Bi = g_Bi[fo];

                    float Bx_r = Br * x_r - Bi * x_i;
                    float Bx_i = Br * x_i + Bi * x_r;
                    float inp_r = dl_r * ig_r * Bx_r;
                    float inp_i = dl_i * ig_i * Bx_i;

                    float m11 = fg_r * Ar, m12 = -fg_r * Ai;
                    float m21 = fg_i * Ai, m22 = fg_i * Ar;

                    float hr = inp_r, hi = inp_i;  // step 1 from h0 = 0
#pragma unroll
                    for (int t = 1; t < 16; ++t) {
                        float nr = fmaf(m11, hr, fmaf(m12, hi, inp_r));
                        float ni = fmaf(m21, hr, fmaf(m22, hi, inp_i));
                        hr = nr; hi = ni;
                    }

                    size_t ob = ((size_t)(b * 128 + h) * 128 + w) * 128;
                    out[ob + m] = hr;
                    out[ob + m + 64] = hi;
                }
    }
}

// ---------------------------------------------------------------------------
// Launch. Inputs (metadata order): x_ri, Wf, bf, Wi, bi, Wd, bd,
//                                  A_real, A_imag, B_real, B_imag
// ---------------------------------------------------------------------------
extern "C" void kernel_launch(void* const* d_in, const int* in_sizes, int n_in,
                              void* d_out, int out_size) {
    (void)in_sizes; (void)n_in; (void)out_size;
    const float* x      = (const float*)d_in[0];
    const float* Wf     = (const float*)d_in[1];
    const float* bf     = (const float*)d_in[2];
    const float* Wi     = (const float*)d_in[3];
    const float* bi     = (const float*)d_in[4];
    const float* Wd     = (const float*)d_in[5];
    const float* bd     = (const float*)d_in[6];
    const float* A_real = (const float*)d_in[7];
    const float* A_imag = (const float*)d_in[8];
    const float* B_real = (const float*)d_in[9];
    const float* B_imag = (const float*)d_in[10];
    float* out = (float*)d_out;

    cudaFuncSetAttribute(fused_main, cudaFuncAttributeMaxDynamicSharedMemorySize,
                         SMEM_BYTES);

    freq_rows<<<128 * 7, 64>>>(A_real, A_imag, B_real, B_imag);
    freq_cols<<<128 * 128, 64>>>();
    fused_main<<<16 * 128, 256, SMEM_BYTES>>>(x, Wf, bf, Wi, bi, Wd, bd, out);
}

// round 4
// speedup vs baseline: 2.0468x; 2.0468x over previous
#include <cuda_runtime.h>
#include <cstdint>

// ============================================================================
// StableFourierConvSSM fused kernel, round 4.
// tcgen05 is NOT available on this toolchain (PTX targets sm_100 without 'a';
// round-3 ptxas rejected all tcgen05). Core GEMM stays on the proven
// mma.sync.m16n8k8 tf32 path from round 2 (718us). This round removes the
// measured-or-modeled overheads around it:
//   - W panels pre-permuted + tf32-rounded ONCE into __device__ global
//     (pack_w kernel); fused_main copies them coalesced, no per-CTA permute.
//   - freq kernels packed (Ar,Ai,Br,Bi) float4 in [h][c][w] -> fully
//     coalesced epilogue loads.
//   - fast transcendentals (__expf/__logf/__fdividef) in the epilogue.
// Shapes: B=16, H=128, W=128, C=64, C2=128, K=7, T=16.
// ============================================================================

#define SX_STRIDE 132   // bank(4w+m)%32 conflict-free A-frag + epilogue x loads
#define SW_STRIDE 72    // conflict-free B-frag loads
#define SMEM_FLOATS (128 * SX_STRIDE + 128 * SW_STRIDE + 384)
#define SMEM_BYTES (SMEM_FLOATS * 4)   // 105,984 B

// Packed freq kernels, layout [h][c][w] float4 = (Ar, Ai, Br, Bi)
__device__ float4 g_AB[128 * 64 * 128];
// Separable-DFT intermediate, layout [(u*7+q)*64 + c]
__device__ float g_GAr[128 * 7 * 64];
__device__ float g_GAi[128 * 7 * 64];
__device__ float g_GBr[128 * 7 * 64];
__device__ float g_GBi[128 * 7 * 64];
// Pre-permuted tf32 W panels: [(gate*2+hf)][k=128][j=64]
__device__ float g_Wpk[6 * 128 * 64];

__device__ __forceinline__ uint32_t f2tf32(float x) {
    uint32_t u;
    asm("cvt.rna.tf32.f32 %0, %1;" : "=r"(u) : "f"(x));
    return u;
}

__device__ __forceinline__ void mma_tf32(float d[4], const uint32_t a[4],
                                         uint32_t b0, uint32_t b1) {
    asm("mma.sync.aligned.m16n8k8.row.col.f32.tf32.tf32.f32 "
        "{%0,%1,%2,%3}, {%4,%5,%6,%7}, {%8,%9}, {%0,%1,%2,%3};"
        : "+f"(d[0]), "+f"(d[1]), "+f"(d[2]), "+f"(d[3])
        : "r"(a[0]), "r"(a[1]), "r"(a[2]), "r"(a[3]), "r"(b0), "r"(b1));
}

__device__ __forceinline__ float sigm_f(float z) {
    return __fdividef(1.0f, 1.0f + __expf(-z));
}
__device__ __forceinline__ float softplus_f(float z) {
    return (z > 20.0f) ? z : __logf(1.0f + __expf(z));
}

// ---------------------------------------------------------------------------
// W pre-pack: permute columns so adjacent output cols are (real c, imag c)
// pairs, round to tf32. grid = 6*128 rows, 64 threads.
// row = (gate*2+hf)*128 + k ; col j -> orig c = hf*32 + (j>>1) + (j&1)*64
// ---------------------------------------------------------------------------
__global__ void pack_w(const float* __restrict__ Wf, const float* __restrict__ Wi,
                       const float* __restrict__ Wd) {
    int row = blockIdx.x;
    int j = threadIdx.x;
    int gh = row >> 7, k = row & 127;
    int gate = gh >> 1, hf = gh & 1;
    const float* W = (gate == 0) ? Wf : (gate == 1) ? Wi : Wd;
    int c = hf * 32 + (j >> 1) + ((j & 1) << 6);
    g_Wpk[row * 64 + j] = __uint_as_float(f2tf32(W[k * 128 + c]));
}

// ---------------------------------------------------------------------------
// Stage 1: G[c,u,q] = sum_p kern[c,p,q] * exp(-2*pi*i * u*(p+60)/128)
// ---------------------------------------------------------------------------
__global__ void freq_rows(const float* __restrict__ A_real, const float* __restrict__ A_imag,
                          const float* __restrict__ B_real, const float* __restrict__ B_imag) {
    __shared__ float tc[128], ts[128];
    int t = threadIdx.x;  // 64
    for (int k = t; k < 128; k += 64) {
        float s, c;
        sincospif((float)k / 64.0f, &s, &c);  // angle = 2*pi*k/128
        tc[k] = c; ts[k] = s;
    }
    __syncthreads();
    int u = blockIdx.x / 7, q = blockIdx.x % 7, c = t;
    float gar = 0.f, gai = 0.f, gbr = 0.f, gbi = 0.f;
#pragma unroll
    for (int p = 0; p < 7; ++p) {
        int idx = (u * (p + 60)) & 127;
        float co = tc[idx], si = ts[idx];  // exp(-i t) = co - i si
        float kr = A_real[c * 49 + p * 7 + q], ki = A_imag[c * 49 + p * 7 + q];
        gar += kr * co + ki * si; gai += ki * co - kr * si;
        kr = B_real[c * 49 + p * 7 + q]; ki = B_imag[c * 49 + p * 7 + q];
        gbr += kr * co + ki * si; gbi += ki * co - kr * si;
    }
    int o = (u * 7 + q) * 64 + c;
    g_GAr[o] = gar; g_GAi[o] = gai; g_GBr[o] = gbr; g_GBi[o] = gbi;
}

// ---------------------------------------------------------------------------
// Stage 2: col DFT + A stability scaling; store packed [h][c][w] float4.
// ---------------------------------------------------------------------------
__global__ void freq_cols() {
    __shared__ float tc[128], ts[128];
    int t = threadIdx.x;  // 64
    for (int k = t; k < 128; k += 64) {
        float s, c;
        sincospif((float)k / 64.0f, &s, &c);
        tc[k] = c; ts[k] = s;
    }
    __syncthreads();
    int u = blockIdx.x >> 7, v = blockIdx.x & 127, c = t;
    float ar = 0.f, ai = 0.f, br = 0.f, bi = 0.f;
#pragma unroll
    for (int q = 0; q < 7; ++q) {
        int idx = (v * (q + 60)) & 127;
        float co = tc[idx], si = ts[idx];
        int o = (u * 7 + q) * 64 + c;
        float gr = g_GAr[o], gi = g_GAi[o];
        ar += gr * co + gi * si; ai += gi * co - gr * si;
        gr = g_GBr[o]; gi = g_GBi[o];
        br += gr * co + gi * si; bi += gi * co - gr * si;
    }
    float mag = sqrtf(ar * ar + ai * ai + 1e-8f);
    float sc = 0.95f * (1.0f / (1.0f + expf(-mag))) / (mag + 1e-8f);
    g_AB[(u * 64 + c) * 128 + v] = make_float4(ar * sc, ai * sc, br, bi);
}

// ---------------------------------------------------------------------------
// Fused main. One CTA per (b,h): M=128 w-rows, K=128, 3 gate GEMMs.
// 8 warps: wm=warp>>1 (32-row strip), wn=warp&1 (32-col half of 64-col panel).
// ---------------------------------------------------------------------------
__global__ void __launch_bounds__(256)
fused_main(const float* __restrict__ x,
           const float* __restrict__ bf, const float* __restrict__ bi_,
           const float* __restrict__ bd, float* __restrict__ out) {
    extern __shared__ float smem[];
    float* sX = smem;                          // [128][SX_STRIDE] raw fp32 x
    float* sW = sX + 128 * SX_STRIDE;          // [128][SW_STRIDE] tf32 panel
    float* sB = sW + 128 * SW_STRIDE;          // [384] biases

    const int tid = threadIdx.x;
    const int b = blockIdx.x >> 7;
    const int h = blockIdx.x & 127;

    // stage x tile (coalesced float4)
    {
        const float4* x4 = (const float4*)(x + ((size_t)(b * 128 + h)) * 16384);
        for (int i = tid; i < 128 * 32; i += 256) {
            int r = i >> 5, c4 = i & 31;
            float4 v = x4[i];
            float* d = sX + r * SX_STRIDE + c4 * 4;
            d[0] = v.x; d[1] = v.y; d[2] = v.z; d[3] = v.w;
        }
        for (int i = tid; i < 384; i += 256)
            sB[i] = (i < 128) ? bf[i] : (i < 256) ? bi_[i - 128] : bd[i - 256];
    }

    const int lane = tid & 31;
    const int warp = tid >> 5;
    const int g = lane >> 2;       // row within 8
    const int t4 = lane & 3;
    const int wm = warp >> 1;      // 32-row strip
    const int wn = warp & 1;       // 32-col half
    const int rbase = wm * 32;

    for (int hf = 0; hf < 2; ++hf) {
        float acc[3][2][4][4];  // [gate][mtile][ntile][frag]

#pragma unroll
        for (int gate = 0; gate < 3; ++gate) {
            __syncthreads();  // previous pass done reading sW (and x staged)
            // coalesced copy of pre-packed panel (no permute, no cvt)
            {
                const float4* src = (const float4*)(g_Wpk + (gate * 2 + hf) * 8192);
                for (int i = tid; i < 2048; i += 256) {
                    int k = i >> 4, j4 = i & 15;
                    *(float4*)&sW[k * SW_STRIDE + j4 * 4] = src[i];
                }
            }
            __syncthreads();

#pragma unroll
            for (int mt = 0; mt < 2; ++mt)
#pragma unroll
                for (int nt = 0; nt < 4; ++nt)
#pragma unroll
                    for (int r = 0; r < 4; ++r)
                        acc[gate][mt][nt][r] = 0.0f;

#pragma unroll 4
            for (int kt = 0; kt < 16; ++kt) {
                int k0 = kt * 8;
                uint32_t a[2][4];
#pragma unroll
                for (int mt = 0; mt < 2; ++mt) {
                    const float* ab = sX + (rbase + 16 * mt + g) * SX_STRIDE;
                    a[mt][0] = f2tf32(ab[k0 + t4]);
                    a[mt][1] = f2tf32(ab[8 * SX_STRIDE + k0 + t4]);
                    a[mt][2] = f2tf32(ab[k0 + t4 + 4]);
                    a[mt][3] = f2tf32(ab[8 * SX_STRIDE + k0 + t4 + 4]);
                }
#pragma unroll
                for (int nt = 0; nt < 4; ++nt) {
                    int jc = wn * 32 + nt * 8 + g;
                    uint32_t b0 = __float_as_uint(sW[(k0 + t4) * SW_STRIDE + jc]);
                    uint32_t b1 = __float_as_uint(sW[(k0 + t4 + 4) * SW_STRIDE + jc]);
                    mma_tf32(acc[gate][0][nt], a[0], b0, b1);
                    mma_tf32(acc[gate][1][nt], a[1], b0, b1);
                }
            }
        }

        // ---- epilogue: activations + complex input + T=16 recurrence ----
#pragma unroll
        for (int mt = 0; mt < 2; ++mt)
#pragma unroll
            for (int rr = 0; rr < 2; ++rr)
#pragma unroll
                for (int nt = 0; nt < 4; ++nt) {
                    const int w = rbase + 16 * mt + g + 8 * rr;
                    const int m = hf * 32 + wn * 16 + nt * 4 + t4;  // channel 0..63

                    float zf_r = acc[0][mt][nt][2 * rr];
                    float zf_i = acc[0][mt][nt][2 * rr + 1];
                    float zi_r = acc[1][mt][nt][2 * rr];
                    float zi_i = acc[1][mt][nt][2 * rr + 1];
                    float zd_r = acc[2][mt][nt][2 * rr];
                    float zd_i = acc[2][mt][nt][2 * rr + 1];

                    float fg_r = sigm_f(zf_r + sB[m] + 2.0f);
                    float fg_i = sigm_f(zf_i + sB[m + 64] + 2.0f);
                    float ig_r = sigm_f(zi_r + sB[128 + m]);
                    float ig_i = sigm_f(zi_i + sB[128 + m + 64]);
                    float dl_r = 0.1f * softplus_f(zd_r + sB[256 + m]);
                    float dl_i = 0.1f * softplus_f(zd_i + sB[256 + m + 64]);

                    float x_r = sX[w * SX_STRIDE + m];
                    float x_i = sX[w * SX_STRIDE + m + 64];

                    float4 AB = g_AB[(h * 64 + m) * 128 + w];  // (Ar,Ai,Br,Bi)

                    float Bx_r = AB.z * x_r - AB.w * x_i;
                    float Bx_i = AB.z * x_i + AB.w * x_r;
                    float inp_r = dl_r * ig_r * Bx_r;
                    float inp_i = dl_i * ig_i * Bx_i;

                    float m11 = fg_r * AB.x, m12 = -fg_r * AB.y;
                    float m21 = fg_i * AB.y, m22 = fg_i * AB.x;

                    float hr = inp_r, hi = inp_i;  // step 1 from h0 = 0
#pragma unroll
                    for (int t = 1; t < 16; ++t) {
                        float nr = fmaf(m11, hr, fmaf(m12, hi, inp_r));
                        float ni = fmaf(m21, hr, fmaf(m22, hi, inp_i));
                        hr = nr; hi = ni;
                    }

                    size_t ob = ((size_t)(b * 128 + h) * 128 + w) * 128;
                    out[ob + m] = hr;
                    out[ob + m + 64] = hi;
                }
    }
}

// ---------------------------------------------------------------------------
// Launch. Inputs: x_ri, Wf, bf, Wi, bi, Wd, bd, A_real, A_imag, B_real, B_imag
// ---------------------------------------------------------------------------
extern "C" void kernel_launch(void* const* d_in, const int* in_sizes, int n_in,
                              void* d_out, int out_size) {
    (void)in_sizes; (void)n_in; (void)out_size;
    const float* x      = (const float*)d_in[0];
    const float* Wf     = (const float*)d_in[1];
    const float* bf     = (const float*)d_in[2];
    const float* Wi     = (const float*)d_in[3];
    const float* bi     = (const float*)d_in[4];
    const float* Wd     = (const float*)d_in[5];
    const float* bd     = (const float*)d_in[6];
    const float* A_real = (const float*)d_in[7];
    const float* A_imag = (const float*)d_in[8];
    const float* B_real = (const float*)d_in[9];
    const float* B_imag = (const float*)d_in[10];
    float* out = (float*)d_out;

    cudaFuncSetAttribute(fused_main, cudaFuncAttributeMaxDynamicSharedMemorySize,
                         SMEM_BYTES);

    pack_w<<<6 * 128, 64>>>(Wf, Wi, Wd);
    freq_rows<<<128 * 7, 64>>>(A_real, A_imag, B_real, B_imag);
    freq_cols<<<128 * 128, 64>>>();
    fused_main<<<16 * 128, 256, SMEM_BYTES>>>(x, bf, bi, bd, out);
}